// round 3
// baseline (speedup 1.0000x reference)
#include <cuda_runtime.h>
#include <math.h>

#define BB 32
#define CC 256
#define HH 64
#define WW 64
#define EPS 1e-5f

// ---- scratch (static device globals; no cudaMalloc anywhere) ----
__device__ float g_pool_hw_max[BB*HH*WW];   // [B][H][W]
__device__ float g_pool_hw_sum[BB*HH*WW];
__device__ float g_pool_cw_max[BB*CC*WW];   // [B][C][W]
__device__ float g_pool_cw_sum[BB*CC*WW];
__device__ float g_pool_ch_max[BB*HH*CC];   // [B][H][C]
__device__ float g_pool_ch_sum[BB*HH*CC];
__device__ float g_gate_hw[BB*HH*WW];       // [B][H][W]
__device__ float g_gate_cw[BB*CC*WW];       // [B][C][W]
__device__ float g_gate_ch[BB*HH*CC];       // [B][H][C]

__device__ __forceinline__ void atomicMaxFloat(float* addr, float value) {
    if (value >= 0.f) atomicMax((int*)addr, __float_as_int(value));
    else              atomicMin((unsigned int*)addr, __float_as_uint(value));
}

// ---- kernel 0: init the atomic-accumulated hw pool ----
__global__ void init_hw_pool_kernel() {
    int i = blockIdx.x * blockDim.x + threadIdx.x;
    if (i < BB*HH*WW) {
        g_pool_hw_max[i] = -INFINITY;
        g_pool_hw_sum[i] = 0.f;
    }
}

// ---- kernel 1: fused BN + triple (max,sum) pooling ----
// grid: (C/TC, B), block: 256 threads (8 warps). Each block: full H, full W, TC channels.
#define TC 16
__global__ __launch_bounds__(256) void pool_kernel(
    const float* __restrict__ x,
    const float* __restrict__ gamma, const float* __restrict__ beta,
    const float* __restrict__ mean,  const float* __restrict__ var)
{
    __shared__ float sm_max[8][64];
    __shared__ float sm_sum[8][64];
    const int b    = blockIdx.y;
    const int c0   = blockIdx.x * TC;
    const int tid  = threadIdx.x;
    const int warp = tid >> 5;
    const int lane = tid & 31;

    float2 hmax[8], hsum[8];
    #pragma unroll
    for (int i = 0; i < 8; i++) {
        hmax[i] = make_float2(-INFINITY, -INFINITY);
        hsum[i] = make_float2(0.f, 0.f);
    }

    for (int ci = 0; ci < TC; ci++) {
        const int c = c0 + ci;
        const float sc = __ldg(&gamma[c]) * rsqrtf(__ldg(&var[c]) + EPS);
        const float sh = __ldg(&beta[c]) - __ldg(&mean[c]) * sc;

        float2 cmax = make_float2(-INFINITY, -INFINITY);
        float2 csum = make_float2(0.f, 0.f);

        #pragma unroll
        for (int hi = 0; hi < 8; hi++) {
            const int h = warp * 8 + hi;
            const float2* row = (const float2*)(x + (((size_t)b*CC + c)*HH + h)*WW);
            float2 v = __ldg(&row[lane]);
            float2 xn = make_float2(fmaf(v.x, sc, sh), fmaf(v.y, sc, sh));

            // ch pool: reduce over W within this warp
            float rm = fmaxf(xn.x, xn.y);
            float rs = xn.x + xn.y;
            #pragma unroll
            for (int o = 16; o; o >>= 1) {
                rm = fmaxf(rm, __shfl_xor_sync(0xffffffffu, rm, o));
                rs += __shfl_xor_sync(0xffffffffu, rs, o);
            }
            if (lane == 0) {
                size_t idx = ((size_t)b*HH + h)*CC + c;
                g_pool_ch_max[idx] = rm;
                g_pool_ch_sum[idx] = rs;
            }

            // cw pool accumulators (reduce over H)
            cmax.x = fmaxf(cmax.x, xn.x); cmax.y = fmaxf(cmax.y, xn.y);
            csum.x += xn.x;               csum.y += xn.y;

            // hw pool accumulators (reduce over C)
            hmax[hi].x = fmaxf(hmax[hi].x, xn.x); hmax[hi].y = fmaxf(hmax[hi].y, xn.y);
            hsum[hi].x += xn.x;                   hsum[hi].y += xn.y;
        }

        // cw: cross-warp combine (each warp covered a distinct 8-row H slice)
        sm_max[warp][2*lane]   = cmax.x;  sm_max[warp][2*lane+1] = cmax.y;
        sm_sum[warp][2*lane]   = csum.x;  sm_sum[warp][2*lane+1] = csum.y;
        __syncthreads();
        if (tid < 64) {
            float m_ = sm_max[0][tid], s_ = sm_sum[0][tid];
            #pragma unroll
            for (int k = 1; k < 8; k++) {
                m_ = fmaxf(m_, sm_max[k][tid]);
                s_ += sm_sum[k][tid];
            }
            size_t idx = ((size_t)b*CC + c)*WW + tid;
            g_pool_cw_max[idx] = m_;
            g_pool_cw_sum[idx] = s_;
        }
        __syncthreads();
    }

    // hw: atomic combine across the C/TC blocks
    #pragma unroll
    for (int hi = 0; hi < 8; hi++) {
        const int h = warp * 8 + hi;
        size_t base = ((size_t)b*HH + h)*WW + 2*lane;
        atomicMaxFloat(&g_pool_hw_max[base],   hmax[hi].x);
        atomicMaxFloat(&g_pool_hw_max[base+1], hmax[hi].y);
        atomicAdd(&g_pool_hw_sum[base],   hsum[hi].x);
        atomicAdd(&g_pool_hw_sum[base+1], hsum[hi].y);
    }
}

// ---- kernel 2: 7x7 conv (2->1, pad 3) + BN(1) + sigmoid on a pooled plane ----
// mode: 0 = hw (R=64,S=64,N=256), 1 = cw (R=256,S=64,N=64), 2 = ch (R=64,S=256,N=64)
__global__ __launch_bounds__(256) void conv_gate_kernel(
    int mode, int R, int S, float invN,
    const float* __restrict__ wts,
    const float* __restrict__ g1, const float* __restrict__ b1,
    const float* __restrict__ m1, const float* __restrict__ v1)
{
    const float* pmax;
    const float* psum;
    float* gate;
    if (mode == 0)      { pmax = g_pool_hw_max; psum = g_pool_hw_sum; gate = g_gate_hw; }
    else if (mode == 1) { pmax = g_pool_cw_max; psum = g_pool_cw_sum; gate = g_gate_cw; }
    else                { pmax = g_pool_ch_max; psum = g_pool_ch_sum; gate = g_gate_ch; }

    __shared__ float sw[98];
    if (threadIdx.x < 98) sw[threadIdx.x] = __ldg(&wts[threadIdx.x]);
    __syncthreads();

    int idx = blockIdx.x * blockDim.x + threadIdx.x;
    int total = BB * R * S;
    if (idx >= total) return;

    int j = idx % S;
    int i = (idx / S) % R;
    int b = idx / (S * R);

    const float* bm = pmax + (size_t)b * R * S;
    const float* bs = psum + (size_t)b * R * S;

    float acc = 0.f;
    #pragma unroll
    for (int di = 0; di < 7; di++) {
        int ii = i + di - 3;
        if (ii < 0 || ii >= R) continue;
        #pragma unroll
        for (int dj = 0; dj < 7; dj++) {
            int jj = j + dj - 3;
            if (jj < 0 || jj >= S) continue;
            size_t p = (size_t)ii * S + jj;
            float mx = __ldg(&bm[p]);
            float mn = __ldg(&bs[p]) * invN;
            acc = fmaf(mx, sw[di*7 + dj], acc);
            acc = fmaf(mn, sw[49 + di*7 + dj], acc);
        }
    }
    float s = __ldg(&g1[0]) * rsqrtf(__ldg(&v1[0]) + EPS);
    float t = __ldg(&b1[0]) - __ldg(&m1[0]) * s;
    float y = fmaf(acc, s, t);
    gate[idx] = 1.f / (1.f + expf(-y));
}

// ---- kernel 3: out = x + (1/3)(g_hw + g_cw + g_ch) * relu(BN(x)) ----
__global__ __launch_bounds__(256) void final_kernel(
    const float* __restrict__ x,
    const float* __restrict__ gamma, const float* __restrict__ beta,
    const float* __restrict__ mean,  const float* __restrict__ var,
    float* __restrict__ out)
{
    size_t t = (size_t)blockIdx.x * blockDim.x + threadIdx.x;  // over N/4
    // layout: w4 fastest (16 float4 per row), then h (64), c (256), b (32)
    int w4 = (int)(t & 15);
    int h  = (int)((t >> 4) & 63);
    int c  = (int)((t >> 10) & 255);
    int b  = (int)(t >> 18);

    float4 xv = __ldg(&((const float4*)x)[t]);

    float sc = __ldg(&gamma[c]) * rsqrtf(__ldg(&var[c]) + EPS);
    float sh = __ldg(&beta[c]) - __ldg(&mean[c]) * sc;

    float4 ghw = __ldg(&((const float4*)g_gate_hw)[((size_t)b*HH + h)*(WW/4) + w4]);
    float4 gcw = __ldg(&((const float4*)g_gate_cw)[((size_t)b*CC + c)*(WW/4) + w4]);
    float  gch = __ldg(&g_gate_ch[((size_t)b*HH + h)*CC + c]);

    const float k = 1.f / 3.f;
    float4 o;
    {
        float xn = fmaf(xv.x, sc, sh); float l = fmaxf(xn, 0.f);
        o.x = fmaf(k * (ghw.x + gcw.x + gch), l, xv.x);
    }
    {
        float xn = fmaf(xv.y, sc, sh); float l = fmaxf(xn, 0.f);
        o.y = fmaf(k * (ghw.y + gcw.y + gch), l, xv.y);
    }
    {
        float xn = fmaf(xv.z, sc, sh); float l = fmaxf(xn, 0.f);
        o.z = fmaf(k * (ghw.z + gcw.z + gch), l, xv.z);
    }
    {
        float xn = fmaf(xv.w, sc, sh); float l = fmaxf(xn, 0.f);
        o.w = fmaf(k * (ghw.w + gcw.w + gch), l, xv.w);
    }
    ((float4*)out)[t] = o;
}

extern "C" void kernel_launch(void* const* d_in, const int* in_sizes, int n_in,
                              void* d_out, int out_size) {
    const float* x     = (const float*)d_in[0];
    const float* gamma = (const float*)d_in[1];
    const float* beta  = (const float*)d_in[2];
    const float* mean  = (const float*)d_in[3];
    const float* var   = (const float*)d_in[4];
    const float* hw_w  = (const float*)d_in[5];
    const float* hw_g  = (const float*)d_in[6];
    const float* hw_b  = (const float*)d_in[7];
    const float* hw_m  = (const float*)d_in[8];
    const float* hw_v  = (const float*)d_in[9];
    const float* cw_w  = (const float*)d_in[10];
    const float* cw_g  = (const float*)d_in[11];
    const float* cw_b  = (const float*)d_in[12];
    const float* cw_m  = (const float*)d_in[13];
    const float* cw_v  = (const float*)d_in[14];
    const float* ch_w  = (const float*)d_in[15];
    const float* ch_g  = (const float*)d_in[16];
    const float* ch_b  = (const float*)d_in[17];
    const float* ch_m  = (const float*)d_in[18];
    const float* ch_v  = (const float*)d_in[19];
    float* out = (float*)d_out;

    // 0) init atomic pool
    init_hw_pool_kernel<<<(BB*HH*WW + 255)/256, 256>>>();

    // 1) fused BN + triple pooling
    dim3 pg(CC/TC, BB);
    pool_kernel<<<pg, 256>>>(x, gamma, beta, mean, var);

    // 2) three tiny conv gates
    conv_gate_kernel<<<(BB*HH*WW + 255)/256, 256>>>(
        0, HH, WW, 1.f/256.f, hw_w, hw_g, hw_b, hw_m, hw_v);
    conv_gate_kernel<<<(BB*CC*WW + 255)/256, 256>>>(
        1, CC, WW, 1.f/64.f, cw_w, cw_g, cw_b, cw_m, cw_v);
    conv_gate_kernel<<<(BB*HH*CC + 255)/256, 256>>>(
        2, HH, CC, 1.f/64.f, ch_w, ch_g, ch_b, ch_m, ch_v);

    // 3) final fused elementwise
    {
        size_t total4 = (size_t)BB*CC*HH*WW/4;
        final_kernel<<<(unsigned)((total4 + 255)/256), 256>>>(
            x, gamma, beta, mean, var, out);
    }
}

// round 4
// speedup vs baseline: 1.2267x; 1.2267x over previous
#include <cuda_runtime.h>
#include <math.h>

#define BB 32
#define CC 256
#define HH 64
#define WW 64
#define EPS 1e-5f

// ---- scratch (static device globals; no cudaMalloc anywhere) ----
__device__ float g_pool_hw_max[BB*HH*WW];   // [B][H][W]
__device__ float g_pool_hw_sum[BB*HH*WW];
__device__ float g_pool_cw_max[BB*CC*WW];   // [B][C][W]
__device__ float g_pool_cw_sum[BB*CC*WW];
__device__ float g_pool_ch_max[BB*HH*CC];   // [B][H][C]
__device__ float g_pool_ch_sum[BB*HH*CC];
__device__ float g_gate_hw[BB*HH*WW];       // [B][H][W]
__device__ float g_gate_cw[BB*CC*WW];       // [B][C][W]
__device__ float g_gate_ch[BB*HH*CC];       // [B][H][C]

__device__ __forceinline__ void atomicMaxFloat(float* addr, float value) {
    if (value >= 0.f) atomicMax((int*)addr, __float_as_int(value));
    else              atomicMin((unsigned int*)addr, __float_as_uint(value));
}

__device__ __forceinline__ float4 f4max(float4 a, float4 b) {
    return make_float4(fmaxf(a.x,b.x), fmaxf(a.y,b.y), fmaxf(a.z,b.z), fmaxf(a.w,b.w));
}
__device__ __forceinline__ float4 f4add(float4 a, float4 b) {
    return make_float4(a.x+b.x, a.y+b.y, a.z+b.z, a.w+b.w);
}

// ---- kernel 0: init the atomic-accumulated hw pool ----
__global__ void init_hw_pool_kernel() {
    int i = blockIdx.x * blockDim.x + threadIdx.x;
    if (i < BB*HH*WW) {
        g_pool_hw_max[i] = -INFINITY;
        g_pool_hw_sum[i] = 0.f;
    }
}

// ---- kernel 1: fused BN + triple (max,sum) pooling, float4 path ----
// grid: (C/TC, B), block 256 = 8 warps. Warp w owns rows 8w..8w+7.
// Lane: sub = lane>>4 selects row parity within a 2-row step, q = lane&15 covers W in float4s.
#define TC 16
__global__ __launch_bounds__(256) void pool_kernel(
    const float* __restrict__ x,
    const float* __restrict__ gamma, const float* __restrict__ beta,
    const float* __restrict__ mean,  const float* __restrict__ var)
{
    __shared__ float smf_max[8*64];
    __shared__ float smf_sum[8*64];
    const int b    = blockIdx.y;
    const int c0   = blockIdx.x * TC;
    const int tid  = threadIdx.x;
    const int w    = tid >> 5;
    const int lane = tid & 31;
    const int sub  = lane >> 4;
    const int q    = lane & 15;

    float4 hmax[4], hsum[4];
    #pragma unroll
    for (int i = 0; i < 4; i++) {
        hmax[i] = make_float4(-INFINITY,-INFINITY,-INFINITY,-INFINITY);
        hsum[i] = make_float4(0.f,0.f,0.f,0.f);
    }

    for (int ci = 0; ci < TC; ci++) {
        const int c = c0 + ci;
        const float sc = __ldg(&gamma[c]) * rsqrtf(__ldg(&var[c]) + EPS);
        const float sh = __ldg(&beta[c]) - __ldg(&mean[c]) * sc;

        float4 cmax = make_float4(-INFINITY,-INFINITY,-INFINITY,-INFINITY);
        float4 csum = make_float4(0.f,0.f,0.f,0.f);

        #pragma unroll
        for (int hj = 0; hj < 4; hj++) {
            const int h = w*8 + hj*2 + sub;
            const float4 v = __ldg((const float4*)(x + (((size_t)b*CC + c)*HH + h)*WW) + q);
            float4 xn;
            xn.x = fmaf(v.x, sc, sh); xn.y = fmaf(v.y, sc, sh);
            xn.z = fmaf(v.z, sc, sh); xn.w = fmaf(v.w, sc, sh);

            hmax[hj] = f4max(hmax[hj], xn); hsum[hj] = f4add(hsum[hj], xn);
            cmax     = f4max(cmax, xn);     csum     = f4add(csum, xn);

            // ch pool: reduce this row's 64 W values over the 16-lane half
            float m = fmaxf(fmaxf(xn.x, xn.y), fmaxf(xn.z, xn.w));
            float s = (xn.x + xn.y) + (xn.z + xn.w);
            #pragma unroll
            for (int o = 8; o; o >>= 1) {
                m = fmaxf(m, __shfl_xor_sync(0xffffffffu, m, o));
                s += __shfl_xor_sync(0xffffffffu, s, o);
            }
            if (q == 0) {
                size_t idx = ((size_t)b*HH + h)*CC + c;
                g_pool_ch_max[idx] = m;
                g_pool_ch_sum[idx] = s;
            }
        }

        // cw: fold the two row-parity halves together
        cmax.x = fmaxf(cmax.x, __shfl_xor_sync(0xffffffffu, cmax.x, 16));
        cmax.y = fmaxf(cmax.y, __shfl_xor_sync(0xffffffffu, cmax.y, 16));
        cmax.z = fmaxf(cmax.z, __shfl_xor_sync(0xffffffffu, cmax.z, 16));
        cmax.w = fmaxf(cmax.w, __shfl_xor_sync(0xffffffffu, cmax.w, 16));
        csum.x += __shfl_xor_sync(0xffffffffu, csum.x, 16);
        csum.y += __shfl_xor_sync(0xffffffffu, csum.y, 16);
        csum.z += __shfl_xor_sync(0xffffffffu, csum.z, 16);
        csum.w += __shfl_xor_sync(0xffffffffu, csum.w, 16);
        if (sub == 0) {
            ((float4*)smf_max)[w*16 + q] = cmax;
            ((float4*)smf_sum)[w*16 + q] = csum;
        }
        __syncthreads();
        if (tid < 64) {
            float m_ = smf_max[tid], s_ = smf_sum[tid];
            #pragma unroll
            for (int k = 1; k < 8; k++) {
                m_ = fmaxf(m_, smf_max[k*64 + tid]);
                s_ += smf_sum[k*64 + tid];
            }
            size_t idx = ((size_t)b*CC + c)*WW + tid;
            g_pool_cw_max[idx] = m_;
            g_pool_cw_sum[idx] = s_;
        }
        __syncthreads();
    }

    // hw: atomic combine across the 16 C-blocks
    #pragma unroll
    for (int hj = 0; hj < 4; hj++) {
        const int h = w*8 + hj*2 + sub;
        size_t base = ((size_t)b*HH + h)*WW + q*4;
        atomicMaxFloat(&g_pool_hw_max[base+0], hmax[hj].x);
        atomicMaxFloat(&g_pool_hw_max[base+1], hmax[hj].y);
        atomicMaxFloat(&g_pool_hw_max[base+2], hmax[hj].z);
        atomicMaxFloat(&g_pool_hw_max[base+3], hmax[hj].w);
        atomicAdd(&g_pool_hw_sum[base+0], hsum[hj].x);
        atomicAdd(&g_pool_hw_sum[base+1], hsum[hj].y);
        atomicAdd(&g_pool_hw_sum[base+2], hsum[hj].z);
        atomicAdd(&g_pool_hw_sum[base+3], hsum[hj].w);
    }
}

// ---- kernel 2: ALL three 7x7 conv gates, fused + smem tiled ----
// 32x32 output tile per block, 38x38 halo (zero-padded), stride-39 smem rows.
// hw: 64x64  -> 2x2 tiles x 32 b = 128 blocks
// cw: 256x64 -> 8x2 tiles x 32 b = 512 blocks
// ch: 64x256 -> 2x8 tiles x 32 b = 512 blocks   (total 1152)
__global__ __launch_bounds__(256) void conv_gate_fused_kernel(
    const float* __restrict__ hw_w, const float* __restrict__ hw_g,
    const float* __restrict__ hw_b, const float* __restrict__ hw_m,
    const float* __restrict__ hw_v,
    const float* __restrict__ cw_w, const float* __restrict__ cw_g,
    const float* __restrict__ cw_b, const float* __restrict__ cw_m,
    const float* __restrict__ cw_v,
    const float* __restrict__ ch_w, const float* __restrict__ ch_g,
    const float* __restrict__ ch_b, const float* __restrict__ ch_m,
    const float* __restrict__ ch_v)
{
    __shared__ float smax[38*39];
    __shared__ float ssum[38*39];
    __shared__ float swt[98];
    __shared__ float sbn[2];

    const int bid = blockIdx.x;
    const int tid = threadIdx.x;

    int R, S, bImg, ti, tj;
    const float *pm, *ps, *wts, *g1, *b1, *m1, *v1;
    float *gate;
    float invN;
    if (bid < 128) {
        R = HH; S = WW; bImg = bid >> 2; int t = bid & 3;
        ti = (t >> 1) * 32; tj = (t & 1) * 32;
        pm = g_pool_hw_max; ps = g_pool_hw_sum; gate = g_gate_hw;
        wts = hw_w; g1 = hw_g; b1 = hw_b; m1 = hw_m; v1 = hw_v; invN = 1.f/256.f;
    } else if (bid < 640) {
        R = CC; S = WW; int t = bid - 128; bImg = t >> 4; t &= 15;
        ti = (t >> 1) * 32; tj = (t & 1) * 32;
        pm = g_pool_cw_max; ps = g_pool_cw_sum; gate = g_gate_cw;
        wts = cw_w; g1 = cw_g; b1 = cw_b; m1 = cw_m; v1 = cw_v; invN = 1.f/64.f;
    } else {
        R = HH; S = CC; int t = bid - 640; bImg = t >> 4; t &= 15;
        ti = (t >> 3) * 32; tj = (t & 7) * 32;
        pm = g_pool_ch_max; ps = g_pool_ch_sum; gate = g_gate_ch;
        wts = ch_w; g1 = ch_g; b1 = ch_b; m1 = ch_m; v1 = ch_v; invN = 1.f/64.f;
    }
    pm += (size_t)bImg * R * S;
    ps += (size_t)bImg * R * S;
    gate += (size_t)bImg * R * S;

    // load halo tiles (zero padding = conv's zero padding)
    for (int i = tid; i < 38*38; i += 256) {
        int li = i / 38, lj = i - li*38;
        int gi = ti + li - 3, gj = tj + lj - 3;
        bool ok = (gi >= 0) & (gi < R) & (gj >= 0) & (gj < S);
        size_t p = (size_t)gi * S + gj;
        smax[li*39 + lj] = ok ? __ldg(&pm[p]) : 0.f;
        ssum[li*39 + lj] = ok ? __ldg(&ps[p]) : 0.f;
    }
    if (tid < 98) swt[tid] = __ldg(&wts[tid]) * (tid >= 49 ? invN : 1.f);
    if (tid == 98) {
        float s = __ldg(&g1[0]) * rsqrtf(__ldg(&v1[0]) + EPS);
        sbn[0] = s;
        sbn[1] = __ldg(&b1[0]) - __ldg(&m1[0]) * s;
    }
    __syncthreads();

    const int ty = tid >> 3;          // 0..31
    const int tx = (tid & 7) * 4;     // 0,4,...,28
    float acc0 = 0.f, acc1 = 0.f, acc2 = 0.f, acc3 = 0.f;

    #pragma unroll
    for (int di = 0; di < 7; di++) {
        float rm[10], rs[10];
        const int rowb = (ty + di) * 39 + tx;
        #pragma unroll
        for (int k = 0; k < 10; k++) {
            rm[k] = smax[rowb + k];
            rs[k] = ssum[rowb + k];
        }
        #pragma unroll
        for (int dj = 0; dj < 7; dj++) {
            const float w1 = swt[di*7 + dj];
            const float w2 = swt[49 + di*7 + dj];
            acc0 = fmaf(rm[dj+0], w1, acc0); acc0 = fmaf(rs[dj+0], w2, acc0);
            acc1 = fmaf(rm[dj+1], w1, acc1); acc1 = fmaf(rs[dj+1], w2, acc1);
            acc2 = fmaf(rm[dj+2], w1, acc2); acc2 = fmaf(rs[dj+2], w2, acc2);
            acc3 = fmaf(rm[dj+3], w1, acc3); acc3 = fmaf(rs[dj+3], w2, acc3);
        }
    }

    const float s = sbn[0], t0 = sbn[1];
    float4 o;
    o.x = 1.f / (1.f + expf(-fmaf(acc0, s, t0)));
    o.y = 1.f / (1.f + expf(-fmaf(acc1, s, t0)));
    o.z = 1.f / (1.f + expf(-fmaf(acc2, s, t0)));
    o.w = 1.f / (1.f + expf(-fmaf(acc3, s, t0)));
    *(float4*)(gate + (size_t)(ti + ty) * S + (tj + tx)) = o;
}

// ---- kernel 3: out = x + (1/3)(g_hw + g_cw + g_ch) * relu(BN(x)) ----
__global__ __launch_bounds__(256) void final_kernel(
    const float* __restrict__ x,
    const float* __restrict__ gamma, const float* __restrict__ beta,
    const float* __restrict__ mean,  const float* __restrict__ var,
    float* __restrict__ out)
{
    size_t t = (size_t)blockIdx.x * blockDim.x + threadIdx.x;  // over N/4
    int w4 = (int)(t & 15);
    int h  = (int)((t >> 4) & 63);
    int c  = (int)((t >> 10) & 255);
    int b  = (int)(t >> 18);

    float4 xv = __ldg(&((const float4*)x)[t]);

    float sc = __ldg(&gamma[c]) * rsqrtf(__ldg(&var[c]) + EPS);
    float sh = __ldg(&beta[c]) - __ldg(&mean[c]) * sc;

    float4 ghw = __ldg(&((const float4*)g_gate_hw)[((size_t)b*HH + h)*(WW/4) + w4]);
    float4 gcw = __ldg(&((const float4*)g_gate_cw)[((size_t)b*CC + c)*(WW/4) + w4]);
    float  gch = __ldg(&g_gate_ch[((size_t)b*HH + h)*CC + c]);

    const float k = 1.f / 3.f;
    float4 o;
    { float xn = fmaf(xv.x, sc, sh); float l = fmaxf(xn, 0.f);
      o.x = fmaf(k * (ghw.x + gcw.x + gch), l, xv.x); }
    { float xn = fmaf(xv.y, sc, sh); float l = fmaxf(xn, 0.f);
      o.y = fmaf(k * (ghw.y + gcw.y + gch), l, xv.y); }
    { float xn = fmaf(xv.z, sc, sh); float l = fmaxf(xn, 0.f);
      o.z = fmaf(k * (ghw.z + gcw.z + gch), l, xv.z); }
    { float xn = fmaf(xv.w, sc, sh); float l = fmaxf(xn, 0.f);
      o.w = fmaf(k * (ghw.w + gcw.w + gch), l, xv.w); }
    ((float4*)out)[t] = o;
}

extern "C" void kernel_launch(void* const* d_in, const int* in_sizes, int n_in,
                              void* d_out, int out_size) {
    const float* x     = (const float*)d_in[0];
    const float* gamma = (const float*)d_in[1];
    const float* beta  = (const float*)d_in[2];
    const float* mean  = (const float*)d_in[3];
    const float* var   = (const float*)d_in[4];
    const float* hw_w  = (const float*)d_in[5];
    const float* hw_g  = (const float*)d_in[6];
    const float* hw_b  = (const float*)d_in[7];
    const float* hw_m  = (const float*)d_in[8];
    const float* hw_v  = (const float*)d_in[9];
    const float* cw_w  = (const float*)d_in[10];
    const float* cw_g  = (const float*)d_in[11];
    const float* cw_b  = (const float*)d_in[12];
    const float* cw_m  = (const float*)d_in[13];
    const float* cw_v  = (const float*)d_in[14];
    const float* ch_w  = (const float*)d_in[15];
    const float* ch_g  = (const float*)d_in[16];
    const float* ch_b  = (const float*)d_in[17];
    const float* ch_m  = (const float*)d_in[18];
    const float* ch_v  = (const float*)d_in[19];
    float* out = (float*)d_out;

    // 0) init atomic hw pool
    init_hw_pool_kernel<<<(BB*HH*WW + 255)/256, 256>>>();

    // 1) fused BN + triple pooling
    dim3 pg(CC/TC, BB);
    pool_kernel<<<pg, 256>>>(x, gamma, beta, mean, var);

    // 2) all three conv gates in one launch
    conv_gate_fused_kernel<<<1152, 256>>>(
        hw_w, hw_g, hw_b, hw_m, hw_v,
        cw_w, cw_g, cw_b, cw_m, cw_v,
        ch_w, ch_g, ch_b, ch_m, ch_v);

    // 3) final fused elementwise
    size_t total4 = (size_t)BB*CC*HH*WW/4;
    final_kernel<<<(unsigned)((total4 + 255)/256), 256>>>(
        x, gamma, beta, mean, var, out);
}

// round 5
// speedup vs baseline: 1.7571x; 1.4324x over previous
#include <cuda_runtime.h>
#include <math.h>

#define BB 32
#define CC 256
#define HH 64
#define WW 64
#define EPS 1e-5f

// ---- scratch (static device globals; no cudaMalloc anywhere) ----
__device__ float g_pool_hw_max[BB*HH*WW];   // [B][H][W]
__device__ float g_pool_hw_sum[BB*HH*WW];
__device__ float g_pool_cw_max[BB*CC*WW];   // [B][C][W]
__device__ float g_pool_cw_sum[BB*CC*WW];
__device__ float g_pool_ch_max[BB*HH*CC];   // [B][H][C]
__device__ float g_pool_ch_sum[BB*HH*CC];
__device__ float g_gate_hw[BB*HH*WW];       // [B][H][W]
__device__ float g_gate_cw[BB*CC*WW];       // [B][C][W]
__device__ float g_gate_ch[BB*HH*CC];       // [B][H][C]

__device__ __forceinline__ void atomicMaxFloat(float* addr, float value) {
    if (value >= 0.f) atomicMax((int*)addr, __float_as_int(value));
    else              atomicMin((unsigned int*)addr, __float_as_uint(value));
}

__device__ __forceinline__ float4 f4max(float4 a, float4 b) {
    return make_float4(fmaxf(a.x,b.x), fmaxf(a.y,b.y), fmaxf(a.z,b.z), fmaxf(a.w,b.w));
}
__device__ __forceinline__ float4 f4add(float4 a, float4 b) {
    return make_float4(a.x+b.x, a.y+b.y, a.z+b.z, a.w+b.w);
}

// ---- kernel 0: init the atomic-accumulated hw pool ----
__global__ void init_hw_pool_kernel() {
    int i = blockIdx.x * blockDim.x + threadIdx.x;
    if (i < BB*HH*WW) {
        g_pool_hw_max[i] = -INFINITY;
        g_pool_hw_sum[i] = 0.f;
    }
}

// ---- kernel 1: fused BN + triple (max,sum) pooling, v3 (MLP + ILP) ----
// grid (C/TC, B), 256 threads = 8 warps. Warp w owns rows [8w, 8w+8).
// Lane: sub = lane>>4 (row parity per 2-row step), q = lane&15 (float4 pos in W).
#define TC 16
__global__ __launch_bounds__(256) void pool_kernel(
    const float* __restrict__ x,
    const float* __restrict__ gamma, const float* __restrict__ beta,
    const float* __restrict__ mean,  const float* __restrict__ var)
{
    __shared__ float s_scale[TC], s_shift[TC];
    __shared__ float s_cw_max[4][8][64];   // [ci&3][warp][w]
    __shared__ float s_cw_sum[4][8][64];

    const int b    = blockIdx.y;
    const int c0   = blockIdx.x * TC;
    const int tid  = threadIdx.x;
    const int w    = tid >> 5;
    const int lane = tid & 31;
    const int sub  = lane >> 4;
    const int q    = lane & 15;

    if (tid < TC) {
        float sc = __ldg(&gamma[c0+tid]) * rsqrtf(__ldg(&var[c0+tid]) + EPS);
        s_scale[tid] = sc;
        s_shift[tid] = __ldg(&beta[c0+tid]) - __ldg(&mean[c0+tid]) * sc;
    }
    __syncthreads();

    float4 hmax[4], hsum[4];
    #pragma unroll
    for (int i = 0; i < 4; i++) {
        hmax[i] = make_float4(-INFINITY,-INFINITY,-INFINITY,-INFINITY);
        hsum[i] = make_float4(0.f,0.f,0.f,0.f);
    }

    const float* xb = x + ((size_t)b*CC + c0)*HH*WW;
    // per-thread float4 offsets within one channel plane
    int off[4];
    #pragma unroll
    for (int hj = 0; hj < 4; hj++) off[hj] = (w*8 + hj*2 + sub)*16 + q;

    // prefetch channel 0
    float4 v[4];
    {
        const float4* p = (const float4*)xb;
        #pragma unroll
        for (int hj = 0; hj < 4; hj++) v[hj] = __ldg(p + off[hj]);
    }

    for (int ci = 0; ci < TC; ci++) {
        float4 cur[4];
        #pragma unroll
        for (int hj = 0; hj < 4; hj++) cur[hj] = v[hj];
        if (ci + 1 < TC) {
            const float4* p = (const float4*)(xb + (size_t)(ci+1)*HH*WW);
            #pragma unroll
            for (int hj = 0; hj < 4; hj++) v[hj] = __ldg(p + off[hj]);
        }

        const float sc = s_scale[ci], sh = s_shift[ci];
        float4 cmax = make_float4(-INFINITY,-INFINITY,-INFINITY,-INFINITY);
        float4 csum = make_float4(0.f,0.f,0.f,0.f);
        float mrow[4], srow[4];

        #pragma unroll
        for (int hj = 0; hj < 4; hj++) {
            float4 xn;
            xn.x = fmaf(cur[hj].x, sc, sh); xn.y = fmaf(cur[hj].y, sc, sh);
            xn.z = fmaf(cur[hj].z, sc, sh); xn.w = fmaf(cur[hj].w, sc, sh);

            hmax[hj] = f4max(hmax[hj], xn); hsum[hj] = f4add(hsum[hj], xn);
            cmax     = f4max(cmax, xn);     csum     = f4add(csum, xn);
            mrow[hj] = fmaxf(fmaxf(xn.x, xn.y), fmaxf(xn.z, xn.w));
            srow[hj] = (xn.x + xn.y) + (xn.z + xn.w);
        }

        // ch: 4 independent 16-lane butterflies, interleaved for ILP
        #pragma unroll
        for (int o = 8; o; o >>= 1) {
            #pragma unroll
            for (int hj = 0; hj < 4; hj++) {
                mrow[hj] = fmaxf(mrow[hj], __shfl_xor_sync(0xffffffffu, mrow[hj], o));
                srow[hj] += __shfl_xor_sync(0xffffffffu, srow[hj], o);
            }
        }
        if (q == 0) {
            #pragma unroll
            for (int hj = 0; hj < 4; hj++) {
                const int h = w*8 + hj*2 + sub;
                size_t idx = ((size_t)b*HH + h)*CC + (c0 + ci);
                g_pool_ch_max[idx] = mrow[hj];
                g_pool_ch_sum[idx] = srow[hj];
            }
        }

        // cw: fold the two row-parity halves, stage per-warp partial in smem
        cmax.x = fmaxf(cmax.x, __shfl_xor_sync(0xffffffffu, cmax.x, 16));
        cmax.y = fmaxf(cmax.y, __shfl_xor_sync(0xffffffffu, cmax.y, 16));
        cmax.z = fmaxf(cmax.z, __shfl_xor_sync(0xffffffffu, cmax.z, 16));
        cmax.w = fmaxf(cmax.w, __shfl_xor_sync(0xffffffffu, cmax.w, 16));
        csum.x += __shfl_xor_sync(0xffffffffu, csum.x, 16);
        csum.y += __shfl_xor_sync(0xffffffffu, csum.y, 16);
        csum.z += __shfl_xor_sync(0xffffffffu, csum.z, 16);
        csum.w += __shfl_xor_sync(0xffffffffu, csum.w, 16);
        if (sub == 0) {
            ((float4*)s_cw_max[ci & 3][w])[q] = cmax;
            ((float4*)s_cw_sum[ci & 3][w])[q] = csum;
        }

        // every 4 channels: one cross-warp reduce phase (all 256 threads)
        if ((ci & 3) == 3) {
            __syncthreads();
            const int cip = tid >> 6;       // 0..3
            const int ww  = tid & 63;       // 0..63
            float m_ = s_cw_max[cip][0][ww];
            float s_ = s_cw_sum[cip][0][ww];
            #pragma unroll
            for (int k = 1; k < 8; k++) {
                m_ = fmaxf(m_, s_cw_max[cip][k][ww]);
                s_ += s_cw_sum[cip][k][ww];
            }
            size_t idx = ((size_t)b*CC + (c0 + (ci - 3) + cip))*WW + ww;
            g_pool_cw_max[idx] = m_;
            g_pool_cw_sum[idx] = s_;
            __syncthreads();
        }
    }

    // hw: atomic combine across the 16 C-group blocks
    #pragma unroll
    for (int hj = 0; hj < 4; hj++) {
        const int h = w*8 + hj*2 + sub;
        size_t base = ((size_t)b*HH + h)*WW + q*4;
        atomicMaxFloat(&g_pool_hw_max[base+0], hmax[hj].x);
        atomicMaxFloat(&g_pool_hw_max[base+1], hmax[hj].y);
        atomicMaxFloat(&g_pool_hw_max[base+2], hmax[hj].z);
        atomicMaxFloat(&g_pool_hw_max[base+3], hmax[hj].w);
        atomicAdd(&g_pool_hw_sum[base+0], hsum[hj].x);
        atomicAdd(&g_pool_hw_sum[base+1], hsum[hj].y);
        atomicAdd(&g_pool_hw_sum[base+2], hsum[hj].z);
        atomicAdd(&g_pool_hw_sum[base+3], hsum[hj].w);
    }
}

// ---- kernel 2: ALL three 7x7 conv gates, fused + smem tiled ----
__global__ __launch_bounds__(256) void conv_gate_fused_kernel(
    const float* __restrict__ hw_w, const float* __restrict__ hw_g,
    const float* __restrict__ hw_b, const float* __restrict__ hw_m,
    const float* __restrict__ hw_v,
    const float* __restrict__ cw_w, const float* __restrict__ cw_g,
    const float* __restrict__ cw_b, const float* __restrict__ cw_m,
    const float* __restrict__ cw_v,
    const float* __restrict__ ch_w, const float* __restrict__ ch_g,
    const float* __restrict__ ch_b, const float* __restrict__ ch_m,
    const float* __restrict__ ch_v)
{
    __shared__ float smax[38*39];
    __shared__ float ssum[38*39];
    __shared__ float swt[98];
    __shared__ float sbn[2];

    const int bid = blockIdx.x;
    const int tid = threadIdx.x;

    int R, S, bImg, ti, tj;
    const float *pm, *ps, *wts, *g1, *b1, *m1, *v1;
    float *gate;
    float invN;
    if (bid < 128) {
        R = HH; S = WW; bImg = bid >> 2; int t = bid & 3;
        ti = (t >> 1) * 32; tj = (t & 1) * 32;
        pm = g_pool_hw_max; ps = g_pool_hw_sum; gate = g_gate_hw;
        wts = hw_w; g1 = hw_g; b1 = hw_b; m1 = hw_m; v1 = hw_v; invN = 1.f/256.f;
    } else if (bid < 640) {
        R = CC; S = WW; int t = bid - 128; bImg = t >> 4; t &= 15;
        ti = (t >> 1) * 32; tj = (t & 1) * 32;
        pm = g_pool_cw_max; ps = g_pool_cw_sum; gate = g_gate_cw;
        wts = cw_w; g1 = cw_g; b1 = cw_b; m1 = cw_m; v1 = cw_v; invN = 1.f/64.f;
    } else {
        R = HH; S = CC; int t = bid - 640; bImg = t >> 4; t &= 15;
        ti = (t >> 3) * 32; tj = (t & 7) * 32;
        pm = g_pool_ch_max; ps = g_pool_ch_sum; gate = g_gate_ch;
        wts = ch_w; g1 = ch_g; b1 = ch_b; m1 = ch_m; v1 = ch_v; invN = 1.f/64.f;
    }
    pm += (size_t)bImg * R * S;
    ps += (size_t)bImg * R * S;
    gate += (size_t)bImg * R * S;

    for (int i = tid; i < 38*38; i += 256) {
        int li = i / 38, lj = i - li*38;
        int gi = ti + li - 3, gj = tj + lj - 3;
        bool ok = (gi >= 0) & (gi < R) & (gj >= 0) & (gj < S);
        size_t p = (size_t)gi * S + gj;
        smax[li*39 + lj] = ok ? __ldg(&pm[p]) : 0.f;
        ssum[li*39 + lj] = ok ? __ldg(&ps[p]) : 0.f;
    }
    if (tid < 98) swt[tid] = __ldg(&wts[tid]) * (tid >= 49 ? invN : 1.f);
    if (tid == 98) {
        float s = __ldg(&g1[0]) * rsqrtf(__ldg(&v1[0]) + EPS);
        sbn[0] = s;
        sbn[1] = __ldg(&b1[0]) - __ldg(&m1[0]) * s;
    }
    __syncthreads();

    const int ty = tid >> 3;
    const int tx = (tid & 7) * 4;
    float acc0 = 0.f, acc1 = 0.f, acc2 = 0.f, acc3 = 0.f;

    #pragma unroll
    for (int di = 0; di < 7; di++) {
        float rm[10], rs[10];
        const int rowb = (ty + di) * 39 + tx;
        #pragma unroll
        for (int k = 0; k < 10; k++) {
            rm[k] = smax[rowb + k];
            rs[k] = ssum[rowb + k];
        }
        #pragma unroll
        for (int dj = 0; dj < 7; dj++) {
            const float w1 = swt[di*7 + dj];
            const float w2 = swt[49 + di*7 + dj];
            acc0 = fmaf(rm[dj+0], w1, acc0); acc0 = fmaf(rs[dj+0], w2, acc0);
            acc1 = fmaf(rm[dj+1], w1, acc1); acc1 = fmaf(rs[dj+1], w2, acc1);
            acc2 = fmaf(rm[dj+2], w1, acc2); acc2 = fmaf(rs[dj+2], w2, acc2);
            acc3 = fmaf(rm[dj+3], w1, acc3); acc3 = fmaf(rs[dj+3], w2, acc3);
        }
    }

    const float s = sbn[0], t0 = sbn[1];
    float4 o;
    o.x = 1.f / (1.f + expf(-fmaf(acc0, s, t0)));
    o.y = 1.f / (1.f + expf(-fmaf(acc1, s, t0)));
    o.z = 1.f / (1.f + expf(-fmaf(acc2, s, t0)));
    o.w = 1.f / (1.f + expf(-fmaf(acc3, s, t0)));
    *(float4*)(gate + (size_t)(ti + ty) * S + (tj + tx)) = o;
}

// ---- kernel 3: out = x + (1/3)(g_hw + g_cw + g_ch) * relu(BN(x)) ----
__global__ __launch_bounds__(256) void final_kernel(
    const float* __restrict__ x,
    const float* __restrict__ gamma, const float* __restrict__ beta,
    const float* __restrict__ mean,  const float* __restrict__ var,
    float* __restrict__ out)
{
    size_t t = (size_t)blockIdx.x * blockDim.x + threadIdx.x;
    int w4 = (int)(t & 15);
    int h  = (int)((t >> 4) & 63);
    int c  = (int)((t >> 10) & 255);
    int b  = (int)(t >> 18);

    float4 xv = __ldg(&((const float4*)x)[t]);

    float sc = __ldg(&gamma[c]) * rsqrtf(__ldg(&var[c]) + EPS);
    float sh = __ldg(&beta[c]) - __ldg(&mean[c]) * sc;

    float4 ghw = __ldg(&((const float4*)g_gate_hw)[((size_t)b*HH + h)*(WW/4) + w4]);
    float4 gcw = __ldg(&((const float4*)g_gate_cw)[((size_t)b*CC + c)*(WW/4) + w4]);
    float  gch = __ldg(&g_gate_ch[((size_t)b*HH + h)*CC + c]);

    const float k = 1.f / 3.f;
    float4 o;
    { float xn = fmaf(xv.x, sc, sh); float l = fmaxf(xn, 0.f);
      o.x = fmaf(k * (ghw.x + gcw.x + gch), l, xv.x); }
    { float xn = fmaf(xv.y, sc, sh); float l = fmaxf(xn, 0.f);
      o.y = fmaf(k * (ghw.y + gcw.y + gch), l, xv.y); }
    { float xn = fmaf(xv.z, sc, sh); float l = fmaxf(xn, 0.f);
      o.z = fmaf(k * (ghw.z + gcw.z + gch), l, xv.z); }
    { float xn = fmaf(xv.w, sc, sh); float l = fmaxf(xn, 0.f);
      o.w = fmaf(k * (ghw.w + gcw.w + gch), l, xv.w); }
    ((float4*)out)[t] = o;
}

extern "C" void kernel_launch(void* const* d_in, const int* in_sizes, int n_in,
                              void* d_out, int out_size) {
    const float* x     = (const float*)d_in[0];
    const float* gamma = (const float*)d_in[1];
    const float* beta  = (const float*)d_in[2];
    const float* mean  = (const float*)d_in[3];
    const float* var   = (const float*)d_in[4];
    const float* hw_w  = (const float*)d_in[5];
    const float* hw_g  = (const float*)d_in[6];
    const float* hw_b  = (const float*)d_in[7];
    const float* hw_m  = (const float*)d_in[8];
    const float* hw_v  = (const float*)d_in[9];
    const float* cw_w  = (const float*)d_in[10];
    const float* cw_g  = (const float*)d_in[11];
    const float* cw_b  = (const float*)d_in[12];
    const float* cw_m  = (const float*)d_in[13];
    const float* cw_v  = (const float*)d_in[14];
    const float* ch_w  = (const float*)d_in[15];
    const float* ch_g  = (const float*)d_in[16];
    const float* ch_b  = (const float*)d_in[17];
    const float* ch_m  = (const float*)d_in[18];
    const float* ch_v  = (const float*)d_in[19];
    float* out = (float*)d_out;

    init_hw_pool_kernel<<<(BB*HH*WW + 255)/256, 256>>>();

    dim3 pg(CC/TC, BB);
    pool_kernel<<<pg, 256>>>(x, gamma, beta, mean, var);

    conv_gate_fused_kernel<<<1152, 256>>>(
        hw_w, hw_g, hw_b, hw_m, hw_v,
        cw_w, cw_g, cw_b, cw_m, cw_v,
        ch_w, ch_g, ch_b, ch_m, ch_v);

    size_t total4 = (size_t)BB*CC*HH*WW/4;
    final_kernel<<<(unsigned)((total4 + 255)/256), 256>>>(
        x, gamma, beta, mean, var, out);
}

// round 6
// speedup vs baseline: 1.7682x; 1.0063x over previous
#include <cuda_runtime.h>
#include <math.h>

#define BB 32
#define CC 256
#define HH 64
#define WW 64
#define EPS 1e-5f
#define NCG 16   // number of C-group blocks contributing to hw pool

// ---- scratch (static device globals; no cudaMalloc anywhere) ----
__device__ float g_hw_part_max[NCG*BB*HH*WW];  // [cg][B][H][W] partials
__device__ float g_hw_part_sum[NCG*BB*HH*WW];
__device__ float g_pool_hw_max[BB*HH*WW];      // [B][H][W] reduced
__device__ float g_pool_hw_sum[BB*HH*WW];
__device__ float g_pool_cw_max[BB*CC*WW];      // [B][C][W]
__device__ float g_pool_cw_sum[BB*CC*WW];
__device__ float g_pool_ch_max[BB*HH*CC];      // [B][H][C]
__device__ float g_pool_ch_sum[BB*HH*CC];
__device__ float g_gate_hw[BB*HH*WW];          // [B][H][W]
__device__ float g_gate_cw[BB*CC*WW];          // [B][C][W]
__device__ float g_gate_ch[BB*HH*CC];          // [B][H][C]

__device__ __forceinline__ float4 f4max(float4 a, float4 b) {
    return make_float4(fmaxf(a.x,b.x), fmaxf(a.y,b.y), fmaxf(a.z,b.z), fmaxf(a.w,b.w));
}
__device__ __forceinline__ float4 f4add(float4 a, float4 b) {
    return make_float4(a.x+b.x, a.y+b.y, a.z+b.z, a.w+b.w);
}

// ---- kernel 1: fused BN + triple (max,sum) pooling ----
// grid (C/TC, B), 256 threads = 8 warps. Warp w owns rows [8w, 8w+8).
#define TC 16
__global__ __launch_bounds__(256) void pool_kernel(
    const float* __restrict__ x,
    const float* __restrict__ gamma, const float* __restrict__ beta,
    const float* __restrict__ mean,  const float* __restrict__ var)
{
    __shared__ float s_scale[TC], s_shift[TC];
    __shared__ float s_cw_max[4][8][64];   // [ci&3][warp][w]
    __shared__ float s_cw_sum[4][8][64];

    const int b    = blockIdx.y;
    const int cg   = blockIdx.x;
    const int c0   = cg * TC;
    const int tid  = threadIdx.x;
    const int w    = tid >> 5;
    const int lane = tid & 31;
    const int sub  = lane >> 4;
    const int q    = lane & 15;

    if (tid < TC) {
        float sc = __ldg(&gamma[c0+tid]) * rsqrtf(__ldg(&var[c0+tid]) + EPS);
        s_scale[tid] = sc;
        s_shift[tid] = __ldg(&beta[c0+tid]) - __ldg(&mean[c0+tid]) * sc;
    }
    __syncthreads();

    float4 hmax[4], hsum[4];
    #pragma unroll
    for (int i = 0; i < 4; i++) {
        hmax[i] = make_float4(-INFINITY,-INFINITY,-INFINITY,-INFINITY);
        hsum[i] = make_float4(0.f,0.f,0.f,0.f);
    }

    const float* xb = x + ((size_t)b*CC + c0)*HH*WW;
    int off[4];
    #pragma unroll
    for (int hj = 0; hj < 4; hj++) off[hj] = (w*8 + hj*2 + sub)*16 + q;

    // prefetch channel 0
    float4 v[4];
    {
        const float4* p = (const float4*)xb;
        #pragma unroll
        for (int hj = 0; hj < 4; hj++) v[hj] = __ldg(p + off[hj]);
    }

    for (int ci = 0; ci < TC; ci++) {
        float4 cur[4];
        #pragma unroll
        for (int hj = 0; hj < 4; hj++) cur[hj] = v[hj];
        if (ci + 1 < TC) {
            const float4* p = (const float4*)(xb + (size_t)(ci+1)*HH*WW);
            #pragma unroll
            for (int hj = 0; hj < 4; hj++) v[hj] = __ldg(p + off[hj]);
        }

        const float sc = s_scale[ci], sh = s_shift[ci];
        float4 cmax = make_float4(-INFINITY,-INFINITY,-INFINITY,-INFINITY);
        float4 csum = make_float4(0.f,0.f,0.f,0.f);
        float mrow[4], srow[4];

        #pragma unroll
        for (int hj = 0; hj < 4; hj++) {
            float4 xn;
            xn.x = fmaf(cur[hj].x, sc, sh); xn.y = fmaf(cur[hj].y, sc, sh);
            xn.z = fmaf(cur[hj].z, sc, sh); xn.w = fmaf(cur[hj].w, sc, sh);

            hmax[hj] = f4max(hmax[hj], xn); hsum[hj] = f4add(hsum[hj], xn);
            cmax     = f4max(cmax, xn);     csum     = f4add(csum, xn);
            mrow[hj] = fmaxf(fmaxf(xn.x, xn.y), fmaxf(xn.z, xn.w));
            srow[hj] = (xn.x + xn.y) + (xn.z + xn.w);
        }

        // ch: 4 independent 16-lane butterflies, interleaved for ILP
        #pragma unroll
        for (int o = 8; o; o >>= 1) {
            #pragma unroll
            for (int hj = 0; hj < 4; hj++) {
                mrow[hj] = fmaxf(mrow[hj], __shfl_xor_sync(0xffffffffu, mrow[hj], o));
                srow[hj] += __shfl_xor_sync(0xffffffffu, srow[hj], o);
            }
        }
        if (q == 0) {
            #pragma unroll
            for (int hj = 0; hj < 4; hj++) {
                const int h = w*8 + hj*2 + sub;
                size_t idx = ((size_t)b*HH + h)*CC + (c0 + ci);
                g_pool_ch_max[idx] = mrow[hj];
                g_pool_ch_sum[idx] = srow[hj];
            }
        }

        // cw: fold the two row-parity halves, stage per-warp partial in smem
        cmax.x = fmaxf(cmax.x, __shfl_xor_sync(0xffffffffu, cmax.x, 16));
        cmax.y = fmaxf(cmax.y, __shfl_xor_sync(0xffffffffu, cmax.y, 16));
        cmax.z = fmaxf(cmax.z, __shfl_xor_sync(0xffffffffu, cmax.z, 16));
        cmax.w = fmaxf(cmax.w, __shfl_xor_sync(0xffffffffu, cmax.w, 16));
        csum.x += __shfl_xor_sync(0xffffffffu, csum.x, 16);
        csum.y += __shfl_xor_sync(0xffffffffu, csum.y, 16);
        csum.z += __shfl_xor_sync(0xffffffffu, csum.z, 16);
        csum.w += __shfl_xor_sync(0xffffffffu, csum.w, 16);
        if (sub == 0) {
            ((float4*)s_cw_max[ci & 3][w])[q] = cmax;
            ((float4*)s_cw_sum[ci & 3][w])[q] = csum;
        }

        if ((ci & 3) == 3) {
            __syncthreads();
            const int cip = tid >> 6;
            const int ww  = tid & 63;
            float m_ = s_cw_max[cip][0][ww];
            float s_ = s_cw_sum[cip][0][ww];
            #pragma unroll
            for (int k = 1; k < 8; k++) {
                m_ = fmaxf(m_, s_cw_max[cip][k][ww]);
                s_ += s_cw_sum[cip][k][ww];
            }
            size_t idx = ((size_t)b*CC + (c0 + (ci - 3) + cip))*WW + ww;
            g_pool_cw_max[idx] = m_;
            g_pool_cw_sum[idx] = s_;
            __syncthreads();
        }
    }

    // hw: plain vector stores of this C-group's partials (no atomics)
    {
        float4* pm4 = (float4*)g_hw_part_max + (size_t)cg * (BB*HH*WW/4);
        float4* ps4 = (float4*)g_hw_part_sum + (size_t)cg * (BB*HH*WW/4);
        #pragma unroll
        for (int hj = 0; hj < 4; hj++) {
            const int h = w*8 + hj*2 + sub;
            size_t idx = ((size_t)b*HH + h)*(WW/4) + q;
            pm4[idx] = hmax[hj];
            ps4[idx] = hsum[hj];
        }
    }
}

// ---- kernel 1b: fold the 16 hw partial planes ----
__global__ __launch_bounds__(256) void hw_reduce_kernel() {
    const int i = blockIdx.x * blockDim.x + threadIdx.x;   // over BHW/4
    const int STRIDE = BB*HH*WW/4;
    const float4* pm4 = (const float4*)g_hw_part_max;
    const float4* ps4 = (const float4*)g_hw_part_sum;

    float4 m = pm4[i];
    float4 s = ps4[i];
    #pragma unroll
    for (int g = 1; g < NCG; g++) {
        m = f4max(m, pm4[(size_t)g*STRIDE + i]);
        s = f4add(s, ps4[(size_t)g*STRIDE + i]);
    }
    ((float4*)g_pool_hw_max)[i] = m;
    ((float4*)g_pool_hw_sum)[i] = s;
}

// ---- kernel 2: ALL three 7x7 conv gates, fused + smem tiled ----
__global__ __launch_bounds__(256) void conv_gate_fused_kernel(
    const float* __restrict__ hw_w, const float* __restrict__ hw_g,
    const float* __restrict__ hw_b, const float* __restrict__ hw_m,
    const float* __restrict__ hw_v,
    const float* __restrict__ cw_w, const float* __restrict__ cw_g,
    const float* __restrict__ cw_b, const float* __restrict__ cw_m,
    const float* __restrict__ cw_v,
    const float* __restrict__ ch_w, const float* __restrict__ ch_g,
    const float* __restrict__ ch_b, const float* __restrict__ ch_m,
    const float* __restrict__ ch_v)
{
    __shared__ float smax[38*39];
    __shared__ float ssum[38*39];
    __shared__ float swt[98];
    __shared__ float sbn[2];

    const int bid = blockIdx.x;
    const int tid = threadIdx.x;

    int R, S, bImg, ti, tj;
    const float *pm, *ps, *wts, *g1, *b1, *m1, *v1;
    float *gate;
    float invN;
    if (bid < 128) {
        R = HH; S = WW; bImg = bid >> 2; int t = bid & 3;
        ti = (t >> 1) * 32; tj = (t & 1) * 32;
        pm = g_pool_hw_max; ps = g_pool_hw_sum; gate = g_gate_hw;
        wts = hw_w; g1 = hw_g; b1 = hw_b; m1 = hw_m; v1 = hw_v; invN = 1.f/256.f;
    } else if (bid < 640) {
        R = CC; S = WW; int t = bid - 128; bImg = t >> 4; t &= 15;
        ti = (t >> 1) * 32; tj = (t & 1) * 32;
        pm = g_pool_cw_max; ps = g_pool_cw_sum; gate = g_gate_cw;
        wts = cw_w; g1 = cw_g; b1 = cw_b; m1 = cw_m; v1 = cw_v; invN = 1.f/64.f;
    } else {
        R = HH; S = CC; int t = bid - 640; bImg = t >> 4; t &= 15;
        ti = (t >> 3) * 32; tj = (t & 7) * 32;
        pm = g_pool_ch_max; ps = g_pool_ch_sum; gate = g_gate_ch;
        wts = ch_w; g1 = ch_g; b1 = ch_b; m1 = ch_m; v1 = ch_v; invN = 1.f/64.f;
    }
    pm += (size_t)bImg * R * S;
    ps += (size_t)bImg * R * S;
    gate += (size_t)bImg * R * S;

    for (int i = tid; i < 38*38; i += 256) {
        int li = i / 38, lj = i - li*38;
        int gi = ti + li - 3, gj = tj + lj - 3;
        bool ok = (gi >= 0) & (gi < R) & (gj >= 0) & (gj < S);
        size_t p = (size_t)gi * S + gj;
        smax[li*39 + lj] = ok ? __ldg(&pm[p]) : 0.f;
        ssum[li*39 + lj] = ok ? __ldg(&ps[p]) : 0.f;
    }
    if (tid < 98) swt[tid] = __ldg(&wts[tid]) * (tid >= 49 ? invN : 1.f);
    if (tid == 98) {
        float s = __ldg(&g1[0]) * rsqrtf(__ldg(&v1[0]) + EPS);
        sbn[0] = s;
        sbn[1] = __ldg(&b1[0]) - __ldg(&m1[0]) * s;
    }
    __syncthreads();

    const int ty = tid >> 3;
    const int tx = (tid & 7) * 4;
    float acc0 = 0.f, acc1 = 0.f, acc2 = 0.f, acc3 = 0.f;

    #pragma unroll
    for (int di = 0; di < 7; di++) {
        float rm[10], rs[10];
        const int rowb = (ty + di) * 39 + tx;
        #pragma unroll
        for (int k = 0; k < 10; k++) {
            rm[k] = smax[rowb + k];
            rs[k] = ssum[rowb + k];
        }
        #pragma unroll
        for (int dj = 0; dj < 7; dj++) {
            const float w1 = swt[di*7 + dj];
            const float w2 = swt[49 + di*7 + dj];
            acc0 = fmaf(rm[dj+0], w1, acc0); acc0 = fmaf(rs[dj+0], w2, acc0);
            acc1 = fmaf(rm[dj+1], w1, acc1); acc1 = fmaf(rs[dj+1], w2, acc1);
            acc2 = fmaf(rm[dj+2], w1, acc2); acc2 = fmaf(rs[dj+2], w2, acc2);
            acc3 = fmaf(rm[dj+3], w1, acc3); acc3 = fmaf(rs[dj+3], w2, acc3);
        }
    }

    const float s = sbn[0], t0 = sbn[1];
    float4 o;
    o.x = 1.f / (1.f + expf(-fmaf(acc0, s, t0)));
    o.y = 1.f / (1.f + expf(-fmaf(acc1, s, t0)));
    o.z = 1.f / (1.f + expf(-fmaf(acc2, s, t0)));
    o.w = 1.f / (1.f + expf(-fmaf(acc3, s, t0)));
    *(float4*)(gate + (size_t)(ti + ty) * S + (tj + tx)) = o;
}

// ---- kernel 3: out = x + (1/3)(g_hw + g_cw + g_ch) * relu(BN(x)) ----
// Each thread processes 2 adjacent float4 (8 floats, same c/h/b).
__global__ __launch_bounds__(256) void final_kernel(
    const float* __restrict__ x,
    const float* __restrict__ gamma, const float* __restrict__ beta,
    const float* __restrict__ mean,  const float* __restrict__ var,
    float* __restrict__ out)
{
    const size_t t = (size_t)blockIdx.x * blockDim.x + threadIdx.x;  // over N/8
    const int w2 = (int)(t & 7);            // pair index within the row (8 pairs)
    const int h  = (int)((t >> 3) & 63);
    const int c  = (int)((t >> 9) & 255);
    const int b  = (int)(t >> 17);
    const int w4 = w2 * 2;

    const size_t base = t * 2;              // float4 index
    float4 xa = __ldg(&((const float4*)x)[base]);
    float4 xb = __ldg(&((const float4*)x)[base + 1]);

    const float sc = __ldg(&gamma[c]) * rsqrtf(__ldg(&var[c]) + EPS);
    const float sh = __ldg(&beta[c]) - __ldg(&mean[c]) * sc;

    const size_t hwi = ((size_t)b*HH + h)*(WW/4) + w4;
    const size_t cwi = ((size_t)b*CC + c)*(WW/4) + w4;
    float4 ghwa = __ldg(&((const float4*)g_gate_hw)[hwi]);
    float4 ghwb = __ldg(&((const float4*)g_gate_hw)[hwi + 1]);
    float4 gcwa = __ldg(&((const float4*)g_gate_cw)[cwi]);
    float4 gcwb = __ldg(&((const float4*)g_gate_cw)[cwi + 1]);
    const float gch = __ldg(&g_gate_ch[((size_t)b*HH + h)*CC + c]);

    const float k = 1.f / 3.f;
    float4 oa, ob;
    { float xn = fmaf(xa.x, sc, sh); oa.x = fmaf(k*(ghwa.x + gcwa.x + gch), fmaxf(xn,0.f), xa.x); }
    { float xn = fmaf(xa.y, sc, sh); oa.y = fmaf(k*(ghwa.y + gcwa.y + gch), fmaxf(xn,0.f), xa.y); }
    { float xn = fmaf(xa.z, sc, sh); oa.z = fmaf(k*(ghwa.z + gcwa.z + gch), fmaxf(xn,0.f), xa.z); }
    { float xn = fmaf(xa.w, sc, sh); oa.w = fmaf(k*(ghwa.w + gcwa.w + gch), fmaxf(xn,0.f), xa.w); }
    { float xn = fmaf(xb.x, sc, sh); ob.x = fmaf(k*(ghwb.x + gcwb.x + gch), fmaxf(xn,0.f), xb.x); }
    { float xn = fmaf(xb.y, sc, sh); ob.y = fmaf(k*(ghwb.y + gcwb.y + gch), fmaxf(xn,0.f), xb.y); }
    { float xn = fmaf(xb.z, sc, sh); ob.z = fmaf(k*(ghwb.z + gcwb.z + gch), fmaxf(xn,0.f), xb.z); }
    { float xn = fmaf(xb.w, sc, sh); ob.w = fmaf(k*(ghwb.w + gcwb.w + gch), fmaxf(xn,0.f), xb.w); }
    ((float4*)out)[base]     = oa;
    ((float4*)out)[base + 1] = ob;
}

extern "C" void kernel_launch(void* const* d_in, const int* in_sizes, int n_in,
                              void* d_out, int out_size) {
    const float* x     = (const float*)d_in[0];
    const float* gamma = (const float*)d_in[1];
    const float* beta  = (const float*)d_in[2];
    const float* mean  = (const float*)d_in[3];
    const float* var   = (const float*)d_in[4];
    const float* hw_w  = (const float*)d_in[5];
    const float* hw_g  = (const float*)d_in[6];
    const float* hw_b  = (const float*)d_in[7];
    const float* hw_m  = (const float*)d_in[8];
    const float* hw_v  = (const float*)d_in[9];
    const float* cw_w  = (const float*)d_in[10];
    const float* cw_g  = (const float*)d_in[11];
    const float* cw_b  = (const float*)d_in[12];
    const float* cw_m  = (const float*)d_in[13];
    const float* cw_v  = (const float*)d_in[14];
    const float* ch_w  = (const float*)d_in[15];
    const float* ch_g  = (const float*)d_in[16];
    const float* ch_b  = (const float*)d_in[17];
    const float* ch_m  = (const float*)d_in[18];
    const float* ch_v  = (const float*)d_in[19];
    float* out = (float*)d_out;

    // 1) fused BN + triple pooling (hw pool -> 16 partial planes)
    dim3 pg(CC/TC, BB);
    pool_kernel<<<pg, 256>>>(x, gamma, beta, mean, var);

    // 1b) fold hw partials
    hw_reduce_kernel<<<(BB*HH*WW/4)/256, 256>>>();

    // 2) all three conv gates in one launch
    conv_gate_fused_kernel<<<1152, 256>>>(
        hw_w, hw_g, hw_b, hw_m, hw_v,
        cw_w, cw_g, cw_b, cw_m, cw_v,
        ch_w, ch_g, ch_b, ch_m, ch_v);

    // 3) final fused elementwise (2 float4 per thread)
    size_t total8 = (size_t)BB*CC*HH*WW/8;
    final_kernel<<<(unsigned)(total8/256), 256>>>(
        x, gamma, beta, mean, var, out);
}

// round 7
// speedup vs baseline: 1.7692x; 1.0006x over previous
#include <cuda_runtime.h>
#include <math.h>

#define BB 32
#define CC 256
#define HH 64
#define WW 64
#define EPS 1e-5f
#define NCG 16   // number of C-group blocks contributing to hw pool

// ---- scratch (static device globals; no cudaMalloc anywhere) ----
__device__ float g_hw_part_max[NCG*BB*HH*WW];  // [cg][B][H][W] partials
__device__ float g_hw_part_sum[NCG*BB*HH*WW];
__device__ float g_pool_hw_max[BB*HH*WW];      // [B][H][W] reduced
__device__ float g_pool_hw_sum[BB*HH*WW];
__device__ float g_pool_cw_max[BB*CC*WW];      // [B][C][W]
__device__ float g_pool_cw_sum[BB*CC*WW];
__device__ float g_pool_ch_max[BB*HH*CC];      // [B][H][C]
__device__ float g_pool_ch_sum[BB*HH*CC];
__device__ float g_gate_hw[BB*HH*WW];          // [B][H][W]
__device__ float g_gate_cw[BB*CC*WW];          // [B][C][W]
__device__ float g_gate_ch[BB*HH*CC];          // [B][H][C]

__device__ __forceinline__ float4 f4max(float4 a, float4 b) {
    return make_float4(fmaxf(a.x,b.x), fmaxf(a.y,b.y), fmaxf(a.z,b.z), fmaxf(a.w,b.w));
}
__device__ __forceinline__ float4 f4add(float4 a, float4 b) {
    return make_float4(a.x+b.x, a.y+b.y, a.z+b.z, a.w+b.w);
}

// ---- kernel 1: fused BN + triple (max,sum) pooling, v4 (no shuffles) ----
// grid (C/TC, B), 256 threads = 8 warps. Warp w owns rows [8w, 8w+8).
// Lane: sub = lane>>4 (row parity per 2-row step), q = lane&15 (float4 pos in W).
#define TC 16
__global__ __launch_bounds__(256) void pool_kernel(
    const float* __restrict__ x,
    const float* __restrict__ gamma, const float* __restrict__ beta,
    const float* __restrict__ mean,  const float* __restrict__ var)
{
    __shared__ float s_scale[TC], s_shift[TC];
    // ch staging: [buf][row 0..63][q 0..15], padded row stride 20 floats
    __shared__ float s_ch_max[2][64][20];
    __shared__ float s_ch_sum[2][64][20];
    // cw staging: [buf][rowgroup 0..15 = warp*2+sub][w 0..63], padded stride 68
    __shared__ float s_cw_max[2][16][68];
    __shared__ float s_cw_sum[2][16][68];

    const int b    = blockIdx.y;
    const int cg   = blockIdx.x;
    const int c0   = cg * TC;
    const int tid  = threadIdx.x;
    const int w    = tid >> 5;
    const int lane = tid & 31;
    const int sub  = lane >> 4;
    const int q    = lane & 15;

    if (tid < TC) {
        float sc = __ldg(&gamma[c0+tid]) * rsqrtf(__ldg(&var[c0+tid]) + EPS);
        s_scale[tid] = sc;
        s_shift[tid] = __ldg(&beta[c0+tid]) - __ldg(&mean[c0+tid]) * sc;
    }
    __syncthreads();

    float4 hmax[4], hsum[4];
    #pragma unroll
    for (int i = 0; i < 4; i++) {
        hmax[i] = make_float4(-INFINITY,-INFINITY,-INFINITY,-INFINITY);
        hsum[i] = make_float4(0.f,0.f,0.f,0.f);
    }

    const float* xb = x + ((size_t)b*CC + c0)*HH*WW;
    int off[4];
    #pragma unroll
    for (int hj = 0; hj < 4; hj++) off[hj] = (w*8 + hj*2 + sub)*16 + q;

    // prefetch channel 0
    float4 v[4];
    {
        const float4* p = (const float4*)xb;
        #pragma unroll
        for (int hj = 0; hj < 4; hj++) v[hj] = __ldg(p + off[hj]);
    }

    for (int ci = 0; ci < TC; ci++) {
        float4 cur[4];
        #pragma unroll
        for (int hj = 0; hj < 4; hj++) cur[hj] = v[hj];
        if (ci + 1 < TC) {
            const float4* p = (const float4*)(xb + (size_t)(ci+1)*HH*WW);
            #pragma unroll
            for (int hj = 0; hj < 4; hj++) v[hj] = __ldg(p + off[hj]);
        }

        const float sc = s_scale[ci], sh = s_shift[ci];
        const int buf = ci & 1;
        float4 cmax = make_float4(-INFINITY,-INFINITY,-INFINITY,-INFINITY);
        float4 csum = make_float4(0.f,0.f,0.f,0.f);

        #pragma unroll
        for (int hj = 0; hj < 4; hj++) {
            float4 xn;
            xn.x = fmaf(cur[hj].x, sc, sh); xn.y = fmaf(cur[hj].y, sc, sh);
            xn.z = fmaf(cur[hj].z, sc, sh); xn.w = fmaf(cur[hj].w, sc, sh);

            hmax[hj] = f4max(hmax[hj], xn); hsum[hj] = f4add(hsum[hj], xn);
            cmax     = f4max(cmax, xn);     csum     = f4add(csum, xn);

            // ch partial for (row, q): horizontal fold of this thread's 4 W values
            const int row = w*8 + hj*2 + sub;
            s_ch_max[buf][row][q] = fmaxf(fmaxf(xn.x, xn.y), fmaxf(xn.z, xn.w));
            s_ch_sum[buf][row][q] = (xn.x + xn.y) + (xn.z + xn.w);
        }

        // cw partial for this (warp,sub) row-group (accumulated over 4 rows in regs)
        *(float4*)&s_cw_max[buf][w*2 + sub][q*4] = cmax;
        *(float4*)&s_cw_sum[buf][w*2 + sub][q*4] = csum;

        // every 2 channels: fold staged partials with all 256 threads
        if (buf == 1) {
            __syncthreads();
            if (tid < 128) {
                // ch: (cb, h) -> fold 16 q partials
                const int cb = tid & 1;
                const int h  = tid >> 1;
                float4 m0 = *(const float4*)&s_ch_max[cb][h][0];
                float4 m1 = *(const float4*)&s_ch_max[cb][h][4];
                float4 m2 = *(const float4*)&s_ch_max[cb][h][8];
                float4 m3 = *(const float4*)&s_ch_max[cb][h][12];
                float4 s0 = *(const float4*)&s_ch_sum[cb][h][0];
                float4 s1 = *(const float4*)&s_ch_sum[cb][h][4];
                float4 s2 = *(const float4*)&s_ch_sum[cb][h][8];
                float4 s3 = *(const float4*)&s_ch_sum[cb][h][12];
                float4 mm = f4max(f4max(m0, m1), f4max(m2, m3));
                float4 ss = f4add(f4add(s0, s1), f4add(s2, s3));
                float m = fmaxf(fmaxf(mm.x, mm.y), fmaxf(mm.z, mm.w));
                float s = (ss.x + ss.y) + (ss.z + ss.w);
                size_t idx = ((size_t)b*HH + h)*CC + (c0 + ci - 1 + cb);
                g_pool_ch_max[idx] = m;
                g_pool_ch_sum[idx] = s;
            } else {
                // cw: (cb, wcol) -> fold 16 row-group partials
                const int tt = tid - 128;
                const int cb = tt & 1;
                const int wc = tt >> 1;
                float m = s_cw_max[cb][0][wc];
                float s = s_cw_sum[cb][0][wc];
                #pragma unroll
                for (int k = 1; k < 16; k++) {
                    m = fmaxf(m, s_cw_max[cb][k][wc]);
                    s += s_cw_sum[cb][k][wc];
                }
                size_t idx = ((size_t)b*CC + (c0 + ci - 1 + cb))*WW + wc;
                g_pool_cw_max[idx] = m;
                g_pool_cw_sum[idx] = s;
            }
            __syncthreads();
        }
    }

    // hw: plain vector stores of this C-group's partials (no atomics)
    {
        float4* pm4 = (float4*)g_hw_part_max + (size_t)cg * (BB*HH*WW/4);
        float4* ps4 = (float4*)g_hw_part_sum + (size_t)cg * (BB*HH*WW/4);
        #pragma unroll
        for (int hj = 0; hj < 4; hj++) {
            const int h = w*8 + hj*2 + sub;
            size_t idx = ((size_t)b*HH + h)*(WW/4) + q;
            pm4[idx] = hmax[hj];
            ps4[idx] = hsum[hj];
        }
    }
}

// ---- kernel 1b: fold the 16 hw partial planes ----
__global__ __launch_bounds__(256) void hw_reduce_kernel() {
    const int i = blockIdx.x * blockDim.x + threadIdx.x;   // over BHW/4
    const int STRIDE = BB*HH*WW/4;
    const float4* pm4 = (const float4*)g_hw_part_max;
    const float4* ps4 = (const float4*)g_hw_part_sum;

    float4 m = pm4[i];
    float4 s = ps4[i];
    #pragma unroll
    for (int g = 1; g < NCG; g++) {
        m = f4max(m, pm4[(size_t)g*STRIDE + i]);
        s = f4add(s, ps4[(size_t)g*STRIDE + i]);
    }
    ((float4*)g_pool_hw_max)[i] = m;
    ((float4*)g_pool_hw_sum)[i] = s;
}

// ---- kernel 2: ALL three 7x7 conv gates, fused + smem tiled ----
__global__ __launch_bounds__(256) void conv_gate_fused_kernel(
    const float* __restrict__ hw_w, const float* __restrict__ hw_g,
    const float* __restrict__ hw_b, const float* __restrict__ hw_m,
    const float* __restrict__ hw_v,
    const float* __restrict__ cw_w, const float* __restrict__ cw_g,
    const float* __restrict__ cw_b, const float* __restrict__ cw_m,
    const float* __restrict__ cw_v,
    const float* __restrict__ ch_w, const float* __restrict__ ch_g,
    const float* __restrict__ ch_b, const float* __restrict__ ch_m,
    const float* __restrict__ ch_v)
{
    __shared__ float smax[38*39];
    __shared__ float ssum[38*39];
    __shared__ float swt[98];
    __shared__ float sbn[2];

    const int bid = blockIdx.x;
    const int tid = threadIdx.x;

    int R, S, bImg, ti, tj;
    const float *pm, *ps, *wts, *g1, *b1, *m1, *v1;
    float *gate;
    float invN;
    if (bid < 128) {
        R = HH; S = WW; bImg = bid >> 2; int t = bid & 3;
        ti = (t >> 1) * 32; tj = (t & 1) * 32;
        pm = g_pool_hw_max; ps = g_pool_hw_sum; gate = g_gate_hw;
        wts = hw_w; g1 = hw_g; b1 = hw_b; m1 = hw_m; v1 = hw_v; invN = 1.f/256.f;
    } else if (bid < 640) {
        R = CC; S = WW; int t = bid - 128; bImg = t >> 4; t &= 15;
        ti = (t >> 1) * 32; tj = (t & 1) * 32;
        pm = g_pool_cw_max; ps = g_pool_cw_sum; gate = g_gate_cw;
        wts = cw_w; g1 = cw_g; b1 = cw_b; m1 = cw_m; v1 = cw_v; invN = 1.f/64.f;
    } else {
        R = HH; S = CC; int t = bid - 640; bImg = t >> 4; t &= 15;
        ti = (t >> 3) * 32; tj = (t & 7) * 32;
        pm = g_pool_ch_max; ps = g_pool_ch_sum; gate = g_gate_ch;
        wts = ch_w; g1 = ch_g; b1 = ch_b; m1 = ch_m; v1 = ch_v; invN = 1.f/64.f;
    }
    pm += (size_t)bImg * R * S;
    ps += (size_t)bImg * R * S;
    gate += (size_t)bImg * R * S;

    for (int i = tid; i < 38*38; i += 256) {
        int li = i / 38, lj = i - li*38;
        int gi = ti + li - 3, gj = tj + lj - 3;
        bool ok = (gi >= 0) & (gi < R) & (gj >= 0) & (gj < S);
        size_t p = (size_t)gi * S + gj;
        smax[li*39 + lj] = ok ? __ldg(&pm[p]) : 0.f;
        ssum[li*39 + lj] = ok ? __ldg(&ps[p]) : 0.f;
    }
    if (tid < 98) swt[tid] = __ldg(&wts[tid]) * (tid >= 49 ? invN : 1.f);
    if (tid == 98) {
        float s = __ldg(&g1[0]) * rsqrtf(__ldg(&v1[0]) + EPS);
        sbn[0] = s;
        sbn[1] = __ldg(&b1[0]) - __ldg(&m1[0]) * s;
    }
    __syncthreads();

    const int ty = tid >> 3;
    const int tx = (tid & 7) * 4;
    float acc0 = 0.f, acc1 = 0.f, acc2 = 0.f, acc3 = 0.f;

    #pragma unroll
    for (int di = 0; di < 7; di++) {
        float rm[10], rs[10];
        const int rowb = (ty + di) * 39 + tx;
        #pragma unroll
        for (int k = 0; k < 10; k++) {
            rm[k] = smax[rowb + k];
            rs[k] = ssum[rowb + k];
        }
        #pragma unroll
        for (int dj = 0; dj < 7; dj++) {
            const float w1 = swt[di*7 + dj];
            const float w2 = swt[49 + di*7 + dj];
            acc0 = fmaf(rm[dj+0], w1, acc0); acc0 = fmaf(rs[dj+0], w2, acc0);
            acc1 = fmaf(rm[dj+1], w1, acc1); acc1 = fmaf(rs[dj+1], w2, acc1);
            acc2 = fmaf(rm[dj+2], w1, acc2); acc2 = fmaf(rs[dj+2], w2, acc2);
            acc3 = fmaf(rm[dj+3], w1, acc3); acc3 = fmaf(rs[dj+3], w2, acc3);
        }
    }

    const float s = sbn[0], t0 = sbn[1];
    float4 o;
    o.x = 1.f / (1.f + expf(-fmaf(acc0, s, t0)));
    o.y = 1.f / (1.f + expf(-fmaf(acc1, s, t0)));
    o.z = 1.f / (1.f + expf(-fmaf(acc2, s, t0)));
    o.w = 1.f / (1.f + expf(-fmaf(acc3, s, t0)));
    *(float4*)(gate + (size_t)(ti + ty) * S + (tj + tx)) = o;
}

// ---- kernel 3: out = x + (1/3)(g_hw + g_cw + g_ch) * relu(BN(x)) ----
// (reverted to the proven 1-float4-per-thread version)
__global__ __launch_bounds__(256) void final_kernel(
    const float* __restrict__ x,
    const float* __restrict__ gamma, const float* __restrict__ beta,
    const float* __restrict__ mean,  const float* __restrict__ var,
    float* __restrict__ out)
{
    size_t t = (size_t)blockIdx.x * blockDim.x + threadIdx.x;
    int w4 = (int)(t & 15);
    int h  = (int)((t >> 4) & 63);
    int c  = (int)((t >> 10) & 255);
    int b  = (int)(t >> 18);

    float4 xv = __ldg(&((const float4*)x)[t]);

    float sc = __ldg(&gamma[c]) * rsqrtf(__ldg(&var[c]) + EPS);
    float sh = __ldg(&beta[c]) - __ldg(&mean[c]) * sc;

    float4 ghw = __ldg(&((const float4*)g_gate_hw)[((size_t)b*HH + h)*(WW/4) + w4]);
    float4 gcw = __ldg(&((const float4*)g_gate_cw)[((size_t)b*CC + c)*(WW/4) + w4]);
    float  gch = __ldg(&g_gate_ch[((size_t)b*HH + h)*CC + c]);

    const float k = 1.f / 3.f;
    float4 o;
    { float xn = fmaf(xv.x, sc, sh); float l = fmaxf(xn, 0.f);
      o.x = fmaf(k * (ghw.x + gcw.x + gch), l, xv.x); }
    { float xn = fmaf(xv.y, sc, sh); float l = fmaxf(xn, 0.f);
      o.y = fmaf(k * (ghw.y + gcw.y + gch), l, xv.y); }
    { float xn = fmaf(xv.z, sc, sh); float l = fmaxf(xn, 0.f);
      o.z = fmaf(k * (ghw.z + gcw.z + gch), l, xv.z); }
    { float xn = fmaf(xv.w, sc, sh); float l = fmaxf(xn, 0.f);
      o.w = fmaf(k * (ghw.w + gcw.w + gch), l, xv.w); }
    ((float4*)out)[t] = o;
}

extern "C" void kernel_launch(void* const* d_in, const int* in_sizes, int n_in,
                              void* d_out, int out_size) {
    const float* x     = (const float*)d_in[0];
    const float* gamma = (const float*)d_in[1];
    const float* beta  = (const float*)d_in[2];
    const float* mean  = (const float*)d_in[3];
    const float* var   = (const float*)d_in[4];
    const float* hw_w  = (const float*)d_in[5];
    const float* hw_g  = (const float*)d_in[6];
    const float* hw_b  = (const float*)d_in[7];
    const float* hw_m  = (const float*)d_in[8];
    const float* hw_v  = (const float*)d_in[9];
    const float* cw_w  = (const float*)d_in[10];
    const float* cw_g  = (const float*)d_in[11];
    const float* cw_b  = (const float*)d_in[12];
    const float* cw_m  = (const float*)d_in[13];
    const float* cw_v  = (const float*)d_in[14];
    const float* ch_w  = (const float*)d_in[15];
    const float* ch_g  = (const float*)d_in[16];
    const float* ch_b  = (const float*)d_in[17];
    const float* ch_m  = (const float*)d_in[18];
    const float* ch_v  = (const float*)d_in[19];
    float* out = (float*)d_out;

    // 1) fused BN + triple pooling (hw pool -> 16 partial planes)
    dim3 pg(CC/TC, BB);
    pool_kernel<<<pg, 256>>>(x, gamma, beta, mean, var);

    // 1b) fold hw partials
    hw_reduce_kernel<<<(BB*HH*WW/4)/256, 256>>>();

    // 2) all three conv gates in one launch
    conv_gate_fused_kernel<<<1152, 256>>>(
        hw_w, hw_g, hw_b, hw_m, hw_v,
        cw_w, cw_g, cw_b, cw_m, cw_v,
        ch_w, ch_g, ch_b, ch_m, ch_v);

    // 3) final fused elementwise
    size_t total4 = (size_t)BB*CC*HH*WW/4;
    final_kernel<<<(unsigned)(total4/256), 256>>>(
        x, gamma, beta, mean, var, out);
}